// round 2
// baseline (speedup 1.0000x reference)
#include <cuda_runtime.h>
#include <math.h>

// ---------------------------------------------------------------------------
// EdgeAttention: 4-scale 1x1-conv projections -> nearest-upsample ->
// pairwise per-pixel cosine similarity averaged over locations -> softmax.
//
// Phase 1: per-scale SGEMM  P_s[b][l][o] = sum_c W_s[o][c]*F_s[b][c][l] + bias_s[o]
//          (stored LOCATION-MAJOR so phase 2 reads contiguous 256-float vectors)
// Phase 2: per full-res location, 10 dot products among the 4 projected
//          vectors (with nearest-neighbor source indexing), 6 cosine pair
//          sums accumulated per block into scratch (no atomics).
// Phase 3: deterministic reduction + mean + softmax -> 8x4x4 output.
// ---------------------------------------------------------------------------

#define C256 256

// scratch: projections, location-major per scale
__device__ float g_PT0[8 * 6400 * C256];   // 52.4 MB
__device__ float g_PT1[8 * 1600 * C256];   // 13.1 MB
__device__ float g_PT2[8 *  400 * C256];   //  3.3 MB
__device__ float g_PT3[8 *  100 * C256];   //  0.8 MB
__device__ float g_partials[8 * 50 * 6];

__device__ __forceinline__ float* scale_pt(int s) {
    switch (s) {
        case 0: return g_PT0;
        case 1: return g_PT1;
        case 2: return g_PT2;
        default: return g_PT3;
    }
}

// ---------------------------------------------------------------------------
// Phase 1: SGEMM, BM=BN=128, BK=16, 256 threads, 8x8 microtile (split 64+64
// fragments for conflict-free LDS.128). Output written transposed
// (location-major) with bias added.
// ---------------------------------------------------------------------------
__global__ __launch_bounds__(256, 2)
void gemm_proj(const float* __restrict__ W, const float* __restrict__ F,
               const float* __restrict__ bias, int L, int scale)
{
    __shared__ float As[2][16][128];
    __shared__ float Bs[2][16][128];

    const int tid = threadIdx.x;
    const int b   = blockIdx.z;
    const int m0  = blockIdx.y * 128;
    const int n0  = blockIdx.x * 128;

    const float* Fb = F + (size_t)b * C256 * L;
    float*       Pb = scale_pt(scale) + (size_t)b * L * C256;

    const int ty = tid >> 4;          // 0..15
    const int tx = tid & 15;          // 0..15
    const int aRow = tid >> 1;        // 0..127
    const int aCol = (tid & 1) << 3;  // 0 or 8
    const int bRow = tid >> 4;        // 0..15
    const int bCol = (tid & 15) << 3; // 0..120

    float4 stA0, stA1, stB0, stB1;

    // ---- load tile 0 ----
    {
        const float* wp = W + (m0 + aRow) * C256 + aCol;
        stA0 = *(const float4*)(wp);
        stA1 = *(const float4*)(wp + 4);
        int n = n0 + bCol;
        const float* fp = Fb + (size_t)bRow * L + n;
        stB0 = (n     < L) ? *(const float4*)(fp)     : make_float4(0.f,0.f,0.f,0.f);
        stB1 = (n + 4 < L) ? *(const float4*)(fp + 4) : make_float4(0.f,0.f,0.f,0.f);
    }
    {
        As[0][aCol + 0][aRow] = stA0.x; As[0][aCol + 1][aRow] = stA0.y;
        As[0][aCol + 2][aRow] = stA0.z; As[0][aCol + 3][aRow] = stA0.w;
        As[0][aCol + 4][aRow] = stA1.x; As[0][aCol + 5][aRow] = stA1.y;
        As[0][aCol + 6][aRow] = stA1.z; As[0][aCol + 7][aRow] = stA1.w;
        *(float4*)&Bs[0][bRow][bCol]     = stB0;
        *(float4*)&Bs[0][bRow][bCol + 4] = stB1;
    }
    __syncthreads();

    float acc[8][8];
#pragma unroll
    for (int i = 0; i < 8; ++i)
#pragma unroll
        for (int j = 0; j < 8; ++j) acc[i][j] = 0.f;

    for (int kt = 0; kt < 16; ++kt) {
        const int cur = kt & 1;
        if (kt < 15) {
            const float* wp = W + (m0 + aRow) * C256 + (kt + 1) * 16 + aCol;
            stA0 = *(const float4*)(wp);
            stA1 = *(const float4*)(wp + 4);
            int krow = (kt + 1) * 16 + bRow;
            int n = n0 + bCol;
            const float* fp = Fb + (size_t)krow * L + n;
            stB0 = (n     < L) ? *(const float4*)(fp)     : make_float4(0.f,0.f,0.f,0.f);
            stB1 = (n + 4 < L) ? *(const float4*)(fp + 4) : make_float4(0.f,0.f,0.f,0.f);
        }
#pragma unroll
        for (int kk = 0; kk < 16; ++kk) {
            float4 a0 = *(const float4*)&As[cur][kk][ty * 4];
            float4 a1 = *(const float4*)&As[cur][kk][64 + ty * 4];
            float4 b0 = *(const float4*)&Bs[cur][kk][tx * 4];
            float4 b1 = *(const float4*)&Bs[cur][kk][64 + tx * 4];
            float av[8] = {a0.x, a0.y, a0.z, a0.w, a1.x, a1.y, a1.z, a1.w};
            float bv[8] = {b0.x, b0.y, b0.z, b0.w, b1.x, b1.y, b1.z, b1.w};
#pragma unroll
            for (int i = 0; i < 8; ++i)
#pragma unroll
                for (int j = 0; j < 8; ++j)
                    acc[i][j] += av[i] * bv[j];
        }
        if (kt < 15) {
            const int nxt = cur ^ 1;
            As[nxt][aCol + 0][aRow] = stA0.x; As[nxt][aCol + 1][aRow] = stA0.y;
            As[nxt][aCol + 2][aRow] = stA0.z; As[nxt][aCol + 3][aRow] = stA0.w;
            As[nxt][aCol + 4][aRow] = stA1.x; As[nxt][aCol + 5][aRow] = stA1.y;
            As[nxt][aCol + 6][aRow] = stA1.z; As[nxt][aCol + 7][aRow] = stA1.w;
            *(float4*)&Bs[nxt][bRow][bCol]     = stB0;
            *(float4*)&Bs[nxt][bRow][bCol + 4] = stB1;
        }
        __syncthreads();
    }

    // ---- epilogue: bias + transposed (location-major) store ----
    float bv0[4], bv1[4];
#pragma unroll
    for (int i = 0; i < 4; ++i) {
        bv0[i] = bias[m0 + ty * 4 + i];
        bv1[i] = bias[m0 + 64 + ty * 4 + i];
    }
#pragma unroll
    for (int j = 0; j < 8; ++j) {
        int n = n0 + ((j < 4) ? (tx * 4 + j) : (64 + tx * 4 + (j - 4)));
        if (n < L) {
            float* dst = Pb + (size_t)n * C256 + m0;
            float4 o0 = make_float4(acc[0][j] + bv0[0], acc[1][j] + bv0[1],
                                    acc[2][j] + bv0[2], acc[3][j] + bv0[3]);
            float4 o1 = make_float4(acc[4][j] + bv1[0], acc[5][j] + bv1[1],
                                    acc[6][j] + bv1[2], acc[7][j] + bv1[3]);
            *(float4*)(dst + ty * 4)      = o0;
            *(float4*)(dst + 64 + ty * 4) = o1;
        }
    }
}

// ---------------------------------------------------------------------------
// Phase 2: cosine pair sums. One warp per location iteration; 10 dots
// (4 norms + 6 cross) of 256-dim contiguous vectors; per-block partials.
// ---------------------------------------------------------------------------
__device__ __forceinline__ float dot4(float4 a, float4 b) {
    return a.x * b.x + a.y * b.y + a.z * b.z + a.w * b.w;
}

__global__ __launch_bounds__(256)
void pair_sums()
{
    const int b    = blockIdx.y;
    const int blk  = blockIdx.x;          // 0..49, 128 locations each
    const int warp = threadIdx.x >> 5;    // 0..7
    const int lane = threadIdx.x & 31;

    float acc[6] = {0.f, 0.f, 0.f, 0.f, 0.f, 0.f};

    for (int it = 0; it < 16; ++it) {
        const int l = blk * 128 + warp * 16 + it;
        const int h = l / 80;
        const int w = l - h * 80;
        const float4* x0 = (const float4*)(g_PT0 + ((size_t)(b * 6400 + l)) * C256);
        const float4* x1 = (const float4*)(g_PT1 + ((size_t)(b * 1600 + (h >> 1) * 40 + (w >> 1))) * C256);
        const float4* x2 = (const float4*)(g_PT2 + ((size_t)(b *  400 + (h >> 2) * 20 + (w >> 2))) * C256);
        const float4* x3 = (const float4*)(g_PT3 + ((size_t)(b *  100 + (h >> 3) * 10 + (w >> 3))) * C256);

        float d[10];
#pragma unroll
        for (int k = 0; k < 10; ++k) d[k] = 0.f;

#pragma unroll
        for (int p = 0; p < 2; ++p) {
            float4 v0 = x0[p * 32 + lane];
            float4 v1 = x1[p * 32 + lane];
            float4 v2 = x2[p * 32 + lane];
            float4 v3 = x3[p * 32 + lane];
            d[0] += dot4(v0, v0);
            d[1] += dot4(v0, v1);
            d[2] += dot4(v0, v2);
            d[3] += dot4(v0, v3);
            d[4] += dot4(v1, v1);
            d[5] += dot4(v1, v2);
            d[6] += dot4(v1, v3);
            d[7] += dot4(v2, v2);
            d[8] += dot4(v2, v3);
            d[9] += dot4(v3, v3);
        }
#pragma unroll
        for (int off = 16; off > 0; off >>= 1) {
#pragma unroll
            for (int k = 0; k < 10; ++k)
                d[k] += __shfl_xor_sync(0xFFFFFFFFu, d[k], off);
        }
        if (lane == 0) {
            float nn0 = sqrtf(d[0]);
            float nn1 = sqrtf(d[4]);
            float nn2 = sqrtf(d[7]);
            float nn3 = sqrtf(d[9]);
            acc[0] += d[1] / fmaxf(nn0 * nn1, 1e-8f);
            acc[1] += d[2] / fmaxf(nn0 * nn2, 1e-8f);
            acc[2] += d[3] / fmaxf(nn0 * nn3, 1e-8f);
            acc[3] += d[5] / fmaxf(nn1 * nn2, 1e-8f);
            acc[4] += d[6] / fmaxf(nn1 * nn3, 1e-8f);
            acc[5] += d[8] / fmaxf(nn2 * nn3, 1e-8f);
        }
    }

    __shared__ float sh[8][6];
    if (lane == 0) {
#pragma unroll
        for (int k = 0; k < 6; ++k) sh[warp][k] = acc[k];
    }
    __syncthreads();
    if (threadIdx.x < 6) {
        float s = 0.f;
#pragma unroll
        for (int wq = 0; wq < 8; ++wq) s += sh[wq][threadIdx.x];
        g_partials[((size_t)b * 50 + blk) * 6 + threadIdx.x] = s;
    }
}

// ---------------------------------------------------------------------------
// Phase 3: reduce partials, mean, build symmetric 4x4 (diag == 1), softmax.
// ---------------------------------------------------------------------------
__global__ void finalize(float* __restrict__ out)
{
    const int b = threadIdx.x;
    if (b >= 8) return;
    float s[6] = {0.f, 0.f, 0.f, 0.f, 0.f, 0.f};
    for (int blk = 0; blk < 50; ++blk) {
#pragma unroll
        for (int k = 0; k < 6; ++k)
            s[k] += g_partials[((size_t)b * 50 + blk) * 6 + k];
    }
    const float inv = 1.0f / 6400.0f;
    float a[4][4];
    a[0][0] = a[1][1] = a[2][2] = a[3][3] = 1.0f;
    a[0][1] = a[1][0] = s[0] * inv;
    a[0][2] = a[2][0] = s[1] * inv;
    a[0][3] = a[3][0] = s[2] * inv;
    a[1][2] = a[2][1] = s[3] * inv;
    a[1][3] = a[3][1] = s[4] * inv;
    a[2][3] = a[3][2] = s[5] * inv;

    for (int i = 0; i < 4; ++i) {
        float m = a[i][0];
        for (int j = 1; j < 4; ++j) m = fmaxf(m, a[i][j]);
        float e[4], sum = 0.f;
        for (int j = 0; j < 4; ++j) { e[j] = __expf(a[i][j] - m); sum += e[j]; }
        // use precise expf for accuracy
        sum = 0.f;
        for (int j = 0; j < 4; ++j) { e[j] = expf(a[i][j] - m); sum += e[j]; }
        for (int j = 0; j < 4; ++j) out[b * 16 + i * 4 + j] = e[j] / sum;
    }
}

// ---------------------------------------------------------------------------
extern "C" void kernel_launch(void* const* d_in, const int* in_sizes, int n_in,
                              void* d_out, int out_size)
{
    const float* f[4]  = {nullptr, nullptr, nullptr, nullptr};
    const float* w[4]  = {nullptr, nullptr, nullptr, nullptr};
    const float* bs[4] = {nullptr, nullptr, nullptr, nullptr};
    int wi = 0, bi = 0;
    for (int i = 0; i < n_in; ++i) {
        long sz = in_sizes[i];
        const float* p = (const float*)d_in[i];
        if      (sz == 65536)    { if (wi < 4) w[wi++]  = p; }
        else if (sz == 256)      { if (bi < 4) bs[bi++] = p; }
        else if (sz == 13107200) f[0] = p;   // 8*256*6400
        else if (sz == 3276800)  f[1] = p;   // 8*256*1600
        else if (sz == 819200)   f[2] = p;   // 8*256*400
        else if (sz == 204800)   f[3] = p;   // 8*256*100
    }

    const int Ls[4] = {6400, 1600, 400, 100};
    for (int s = 0; s < 4; ++s) {
        dim3 grid((Ls[s] + 127) / 128, 2, 8);
        gemm_proj<<<grid, 256>>>(w[s], f[s], bs[s], Ls[s], s);
    }
    pair_sums<<<dim3(50, 8), 256>>>();
    finalize<<<1, 32>>>((float*)d_out);
}

// round 3
// speedup vs baseline: 1.0008x; 1.0008x over previous
#include <cuda_runtime.h>
#include <math.h>

// ---------------------------------------------------------------------------
// EdgeAttention: 4-scale 1x1-conv projections -> nearest-upsample ->
// pairwise per-pixel cosine similarity averaged over locations -> softmax.
//
// Phase 1: per-scale SGEMM  P_s[b][l][o] = sum_c W_s[o][c]*F_s[b][c][l] + bias_s[o]
//          (stored LOCATION-MAJOR so phase 2 reads contiguous 256-float vectors)
// Phase 2: per full-res location, 10 dot products among the 4 projected
//          vectors (with nearest-neighbor source indexing), 6 cosine pair
//          sums accumulated per block into scratch (no atomics).
// Phase 3: deterministic reduction + mean + softmax -> 8x4x4 output.
// ---------------------------------------------------------------------------

#define C256 256

// scratch: projections, location-major per scale
__device__ float g_PT0[8 * 6400 * C256];   // 52.4 MB
__device__ float g_PT1[8 * 1600 * C256];   // 13.1 MB
__device__ float g_PT2[8 *  400 * C256];   //  3.3 MB
__device__ float g_PT3[8 *  100 * C256];   //  0.8 MB
__device__ float g_partials[8 * 50 * 6];

__device__ __forceinline__ float* scale_pt(int s) {
    switch (s) {
        case 0: return g_PT0;
        case 1: return g_PT1;
        case 2: return g_PT2;
        default: return g_PT3;
    }
}

// ---------------------------------------------------------------------------
// Phase 1: SGEMM, BM=BN=128, BK=16, 256 threads, 8x8 microtile (split 64+64
// fragments for conflict-free LDS.128). Output written transposed
// (location-major) with bias added.
// ---------------------------------------------------------------------------
__global__ __launch_bounds__(256, 2)
void gemm_proj(const float* __restrict__ W, const float* __restrict__ F,
               const float* __restrict__ bias, int L, int scale)
{
    __shared__ float As[2][16][128];
    __shared__ float Bs[2][16][128];

    const int tid = threadIdx.x;
    const int b   = blockIdx.z;
    const int m0  = blockIdx.y * 128;
    const int n0  = blockIdx.x * 128;

    const float* Fb = F + (size_t)b * C256 * L;
    float*       Pb = scale_pt(scale) + (size_t)b * L * C256;

    const int ty = tid >> 4;          // 0..15
    const int tx = tid & 15;          // 0..15
    const int aRow = tid >> 1;        // 0..127
    const int aCol = (tid & 1) << 3;  // 0 or 8
    const int bRow = tid >> 4;        // 0..15
    const int bCol = (tid & 15) << 3; // 0..120

    float4 stA0, stA1, stB0, stB1;

    // ---- load tile 0 ----
    {
        const float* wp = W + (m0 + aRow) * C256 + aCol;
        stA0 = *(const float4*)(wp);
        stA1 = *(const float4*)(wp + 4);
        int n = n0 + bCol;
        const float* fp = Fb + (size_t)bRow * L + n;
        stB0 = (n     < L) ? *(const float4*)(fp)     : make_float4(0.f,0.f,0.f,0.f);
        stB1 = (n + 4 < L) ? *(const float4*)(fp + 4) : make_float4(0.f,0.f,0.f,0.f);
    }
    {
        As[0][aCol + 0][aRow] = stA0.x; As[0][aCol + 1][aRow] = stA0.y;
        As[0][aCol + 2][aRow] = stA0.z; As[0][aCol + 3][aRow] = stA0.w;
        As[0][aCol + 4][aRow] = stA1.x; As[0][aCol + 5][aRow] = stA1.y;
        As[0][aCol + 6][aRow] = stA1.z; As[0][aCol + 7][aRow] = stA1.w;
        *(float4*)&Bs[0][bRow][bCol]     = stB0;
        *(float4*)&Bs[0][bRow][bCol + 4] = stB1;
    }
    __syncthreads();

    float acc[8][8];
#pragma unroll
    for (int i = 0; i < 8; ++i)
#pragma unroll
        for (int j = 0; j < 8; ++j) acc[i][j] = 0.f;

    for (int kt = 0; kt < 16; ++kt) {
        const int cur = kt & 1;
        if (kt < 15) {
            const float* wp = W + (m0 + aRow) * C256 + (kt + 1) * 16 + aCol;
            stA0 = *(const float4*)(wp);
            stA1 = *(const float4*)(wp + 4);
            int krow = (kt + 1) * 16 + bRow;
            int n = n0 + bCol;
            const float* fp = Fb + (size_t)krow * L + n;
            stB0 = (n     < L) ? *(const float4*)(fp)     : make_float4(0.f,0.f,0.f,0.f);
            stB1 = (n + 4 < L) ? *(const float4*)(fp + 4) : make_float4(0.f,0.f,0.f,0.f);
        }
#pragma unroll
        for (int kk = 0; kk < 16; ++kk) {
            float4 a0 = *(const float4*)&As[cur][kk][ty * 4];
            float4 a1 = *(const float4*)&As[cur][kk][64 + ty * 4];
            float4 b0 = *(const float4*)&Bs[cur][kk][tx * 4];
            float4 b1 = *(const float4*)&Bs[cur][kk][64 + tx * 4];
            float av[8] = {a0.x, a0.y, a0.z, a0.w, a1.x, a1.y, a1.z, a1.w};
            float bv[8] = {b0.x, b0.y, b0.z, b0.w, b1.x, b1.y, b1.z, b1.w};
#pragma unroll
            for (int i = 0; i < 8; ++i)
#pragma unroll
                for (int j = 0; j < 8; ++j)
                    acc[i][j] += av[i] * bv[j];
        }
        if (kt < 15) {
            const int nxt = cur ^ 1;
            As[nxt][aCol + 0][aRow] = stA0.x; As[nxt][aCol + 1][aRow] = stA0.y;
            As[nxt][aCol + 2][aRow] = stA0.z; As[nxt][aCol + 3][aRow] = stA0.w;
            As[nxt][aCol + 4][aRow] = stA1.x; As[nxt][aCol + 5][aRow] = stA1.y;
            As[nxt][aCol + 6][aRow] = stA1.z; As[nxt][aCol + 7][aRow] = stA1.w;
            *(float4*)&Bs[nxt][bRow][bCol]     = stB0;
            *(float4*)&Bs[nxt][bRow][bCol + 4] = stB1;
        }
        __syncthreads();
    }

    // ---- epilogue: bias + transposed (location-major) store ----
    float bv0[4], bv1[4];
#pragma unroll
    for (int i = 0; i < 4; ++i) {
        bv0[i] = bias[m0 + ty * 4 + i];
        bv1[i] = bias[m0 + 64 + ty * 4 + i];
    }
#pragma unroll
    for (int j = 0; j < 8; ++j) {
        int n = n0 + ((j < 4) ? (tx * 4 + j) : (64 + tx * 4 + (j - 4)));
        if (n < L) {
            float* dst = Pb + (size_t)n * C256 + m0;
            float4 o0 = make_float4(acc[0][j] + bv0[0], acc[1][j] + bv0[1],
                                    acc[2][j] + bv0[2], acc[3][j] + bv0[3]);
            float4 o1 = make_float4(acc[4][j] + bv1[0], acc[5][j] + bv1[1],
                                    acc[6][j] + bv1[2], acc[7][j] + bv1[3]);
            *(float4*)(dst + ty * 4)      = o0;
            *(float4*)(dst + 64 + ty * 4) = o1;
        }
    }
}

// ---------------------------------------------------------------------------
// Phase 2: cosine pair sums. One warp per location iteration; 10 dots
// (4 norms + 6 cross) of 256-dim contiguous vectors; per-block partials.
// ---------------------------------------------------------------------------
__device__ __forceinline__ float dot4(float4 a, float4 b) {
    return a.x * b.x + a.y * b.y + a.z * b.z + a.w * b.w;
}

__global__ __launch_bounds__(256)
void pair_sums()
{
    const int b    = blockIdx.y;
    const int blk  = blockIdx.x;          // 0..49, 128 locations each
    const int warp = threadIdx.x >> 5;    // 0..7
    const int lane = threadIdx.x & 31;

    float acc[6] = {0.f, 0.f, 0.f, 0.f, 0.f, 0.f};

    for (int it = 0; it < 16; ++it) {
        const int l = blk * 128 + warp * 16 + it;
        const int h = l / 80;
        const int w = l - h * 80;
        const float4* x0 = (const float4*)(g_PT0 + ((size_t)(b * 6400 + l)) * C256);
        const float4* x1 = (const float4*)(g_PT1 + ((size_t)(b * 1600 + (h >> 1) * 40 + (w >> 1))) * C256);
        const float4* x2 = (const float4*)(g_PT2 + ((size_t)(b *  400 + (h >> 2) * 20 + (w >> 2))) * C256);
        const float4* x3 = (const float4*)(g_PT3 + ((size_t)(b *  100 + (h >> 3) * 10 + (w >> 3))) * C256);

        float d[10];
#pragma unroll
        for (int k = 0; k < 10; ++k) d[k] = 0.f;

#pragma unroll
        for (int p = 0; p < 2; ++p) {
            float4 v0 = x0[p * 32 + lane];
            float4 v1 = x1[p * 32 + lane];
            float4 v2 = x2[p * 32 + lane];
            float4 v3 = x3[p * 32 + lane];
            d[0] += dot4(v0, v0);
            d[1] += dot4(v0, v1);
            d[2] += dot4(v0, v2);
            d[3] += dot4(v0, v3);
            d[4] += dot4(v1, v1);
            d[5] += dot4(v1, v2);
            d[6] += dot4(v1, v3);
            d[7] += dot4(v2, v2);
            d[8] += dot4(v2, v3);
            d[9] += dot4(v3, v3);
        }
#pragma unroll
        for (int off = 16; off > 0; off >>= 1) {
#pragma unroll
            for (int k = 0; k < 10; ++k)
                d[k] += __shfl_xor_sync(0xFFFFFFFFu, d[k], off);
        }
        if (lane == 0) {
            float nn0 = sqrtf(d[0]);
            float nn1 = sqrtf(d[4]);
            float nn2 = sqrtf(d[7]);
            float nn3 = sqrtf(d[9]);
            acc[0] += d[1] / fmaxf(nn0 * nn1, 1e-8f);
            acc[1] += d[2] / fmaxf(nn0 * nn2, 1e-8f);
            acc[2] += d[3] / fmaxf(nn0 * nn3, 1e-8f);
            acc[3] += d[5] / fmaxf(nn1 * nn2, 1e-8f);
            acc[4] += d[6] / fmaxf(nn1 * nn3, 1e-8f);
            acc[5] += d[8] / fmaxf(nn2 * nn3, 1e-8f);
        }
    }

    __shared__ float sh[8][6];
    if (lane == 0) {
#pragma unroll
        for (int k = 0; k < 6; ++k) sh[warp][k] = acc[k];
    }
    __syncthreads();
    if (threadIdx.x < 6) {
        float s = 0.f;
#pragma unroll
        for (int wq = 0; wq < 8; ++wq) s += sh[wq][threadIdx.x];
        g_partials[((size_t)b * 50 + blk) * 6 + threadIdx.x] = s;
    }
}

// ---------------------------------------------------------------------------
// Phase 3: reduce partials, mean, build symmetric 4x4 (diag == 1), softmax.
// ---------------------------------------------------------------------------
__global__ void finalize(float* __restrict__ out)
{
    const int b = threadIdx.x;
    if (b >= 8) return;
    float s[6] = {0.f, 0.f, 0.f, 0.f, 0.f, 0.f};
    for (int blk = 0; blk < 50; ++blk) {
#pragma unroll
        for (int k = 0; k < 6; ++k)
            s[k] += g_partials[((size_t)b * 50 + blk) * 6 + k];
    }
    const float inv = 1.0f / 6400.0f;
    float a[4][4];
    a[0][0] = a[1][1] = a[2][2] = a[3][3] = 1.0f;
    a[0][1] = a[1][0] = s[0] * inv;
    a[0][2] = a[2][0] = s[1] * inv;
    a[0][3] = a[3][0] = s[2] * inv;
    a[1][2] = a[2][1] = s[3] * inv;
    a[1][3] = a[3][1] = s[4] * inv;
    a[2][3] = a[3][2] = s[5] * inv;

    for (int i = 0; i < 4; ++i) {
        float m = a[i][0];
        for (int j = 1; j < 4; ++j) m = fmaxf(m, a[i][j]);
        float e[4], sum = 0.f;
        for (int j = 0; j < 4; ++j) { e[j] = __expf(a[i][j] - m); sum += e[j]; }
        // use precise expf for accuracy
        sum = 0.f;
        for (int j = 0; j < 4; ++j) { e[j] = expf(a[i][j] - m); sum += e[j]; }
        for (int j = 0; j < 4; ++j) out[b * 16 + i * 4 + j] = e[j] / sum;
    }
}

// ---------------------------------------------------------------------------
extern "C" void kernel_launch(void* const* d_in, const int* in_sizes, int n_in,
                              void* d_out, int out_size)
{
    const float* f[4]  = {nullptr, nullptr, nullptr, nullptr};
    const float* w[4]  = {nullptr, nullptr, nullptr, nullptr};
    const float* bs[4] = {nullptr, nullptr, nullptr, nullptr};
    int wi = 0, bi = 0;
    for (int i = 0; i < n_in; ++i) {
        long sz = in_sizes[i];
        const float* p = (const float*)d_in[i];
        if      (sz == 65536)    { if (wi < 4) w[wi++]  = p; }
        else if (sz == 256)      { if (bi < 4) bs[bi++] = p; }
        else if (sz == 13107200) f[0] = p;   // 8*256*6400
        else if (sz == 3276800)  f[1] = p;   // 8*256*1600
        else if (sz == 819200)   f[2] = p;   // 8*256*400
        else if (sz == 204800)   f[3] = p;   // 8*256*100
    }

    const int Ls[4] = {6400, 1600, 400, 100};
    for (int s = 0; s < 4; ++s) {
        dim3 grid((Ls[s] + 127) / 128, 2, 8);
        gemm_proj<<<grid, 256>>>(w[s], f[s], bs[s], Ls[s], s);
    }
    pair_sums<<<dim3(50, 8), 256>>>();
    finalize<<<1, 32>>>((float*)d_out);
}